// round 2
// baseline (speedup 1.0000x reference)
#include <cuda_runtime.h>
#include <math.h>
#include <stdint.h>

// Problem constants (fixed by the dataset): N=8, C=3, R=8, P1=P2=512, n_iter=3
#define P_    262144
#define P2_   131072       // P_/2 (float2 count per (n,r) plane)
#define EPS_  1e-10f

// ---- scratch layout in a __device__ global (no allocations allowed) ----
#define OFF_MEANX   0      // 24  : sum_p X[n,c,p]  (divide by P when used)
#define OFF_S      24      // 24  : current S[c*8+r]
#define OFF_F      48      // 64  : lazy scale f[n*8+r] applied to stored Dt
#define OFF_DTSUM 112      // 64  : sum_p of stored (unscaled) Dt
#define OFF_ACCSUM 176     // 64  : pass accumulator: sum_p Dt_new
#define OFF_GRAM  240      // 288 : pass accumulator: upper-tri Gram (36 per n)
#define OFF_XD    528      // 192 : pass accumulator: sum_p X[c]*Dt_new[r]
#define OFF_CNST  720      // 64  : per-(n,r) affine constant for the update
#define OFF_TAUD  784
#define OFF_GAMMA 785
#define OFF_LAM   786
#define OFF_SNRM  788      // 8   : column norms of S

__device__ float g_s[1024];

__device__ __forceinline__ int triIdx(int r, int r2) {   // r <= r2
    return r * 8 - (r * (r - 1)) / 2 + (r2 - r);
}

// packed f32x2 FMA: d = a*b + d  (both lanes)
__device__ __forceinline__ void ffma2(uint64_t& d, uint64_t a, uint64_t b) {
    asm("fma.rn.f32x2 %0, %1, %2, %0;" : "+l"(d) : "l"(a), "l"(b));
}
__device__ __forceinline__ float f2lo(uint64_t v) {
    return __uint_as_float((unsigned)(v & 0xffffffffu));
}
__device__ __forceinline__ float f2hi(uint64_t v) {
    return __uint_as_float((unsigned)(v >> 32));
}

// ---------------------------------------------------------------------------
// k_init: zero scratch, load S / |gamma| / |lam|
// ---------------------------------------------------------------------------
__global__ void k_init(const float* __restrict__ S,
                       const float* __restrict__ gamma,
                       const float* __restrict__ lam) {
    int tid = threadIdx.x;
    for (int i = tid; i < 1024; i += blockDim.x) g_s[i] = 0.f;
    __syncthreads();
    if (tid < 24) g_s[OFF_S + tid] = S[tid];
    if (tid == 24) g_s[OFF_GAMMA] = fabsf(gamma[0]);
    if (tid == 25) g_s[OFF_LAM]   = fabsf(lam[0]);
}

// ---------------------------------------------------------------------------
// k_meanx: sum_p X[n,c,p] -> g_s[OFF_MEANX + n*3+c]   grid(32, 24), 256 thr
// ---------------------------------------------------------------------------
__global__ void __launch_bounds__(256) k_meanx(const float* __restrict__ X) {
    int y = blockIdx.y;                       // n*3+c
    const float4* Xp = reinterpret_cast<const float4*>(X + (size_t)y * P_);
    int base = blockIdx.x * 2048;
    float s = 0.f;
    #pragma unroll
    for (int l = 0; l < 8; l++) {
        float4 v = Xp[base + l * 256 + threadIdx.x];
        s += v.x + v.y + v.z + v.w;
    }
    #pragma unroll
    for (int o = 16; o; o >>= 1) s += __shfl_xor_sync(0xffffffffu, s, o);
    __shared__ float sw[8];
    if ((threadIdx.x & 31) == 0) sw[threadIdx.x >> 5] = s;
    __syncthreads();
    if (threadIdx.x == 0) {
        float t = 0.f;
        #pragma unroll
        for (int w = 0; w < 8; w++) t += sw[w];
        atomicAdd(&g_s[OFF_MEANX + y], t);
    }
}

// ---------------------------------------------------------------------------
// k_iterA: per-iteration prep. Zero accumulators; compute tau_D, S_nrm,
//          x0[n,c] = (meanX_sum + S·(f⊙Dtsum))/P, cnst[n,r] = tauD*b - thr.
// ---------------------------------------------------------------------------
__global__ void __launch_bounds__(128) k_iterA() {
    int tid = threadIdx.x;
    for (int i = tid; i < 544; i += blockDim.x) g_s[OFF_ACCSUM + i] = 0.f;
    __shared__ float sStS[64], sx0[24];
    __syncthreads();
    if (tid < 64) {                           // StS[r,r2]
        int r = tid >> 3, r2 = tid & 7;
        float a = 0.f;
        #pragma unroll
        for (int c = 0; c < 3; c++) a += g_s[OFF_S + c * 8 + r] * g_s[OFF_S + c * 8 + r2];
        sStS[tid] = a;
    }
    __syncthreads();
    if (tid == 0) {
        float s = 0.f;
        #pragma unroll
        for (int r = 0; r < 8; r++) s += sStS[r * 8 + r];
        g_s[OFF_TAUD] = 1.f / s;
    }
    if (tid >= 32 && tid < 40) {
        int r = tid - 32;
        g_s[OFF_SNRM + r] = sqrtf(sStS[r * 8 + r]);
    }
    if (tid >= 64 && tid < 88) {              // x0[n,c]
        int k = tid - 64, n = k / 3, c = k % 3;
        float acc = g_s[OFF_MEANX + k];
        #pragma unroll
        for (int r = 0; r < 8; r++)
            acc += g_s[OFF_S + c * 8 + r] * g_s[OFF_F + n * 8 + r] * g_s[OFF_DTSUM + n * 8 + r];
        sx0[k] = acc * (1.f / (float)P_);
    }
    __syncthreads();
    if (tid < 64) {                           // cnst[n,r]
        int n = tid >> 3, r = tid & 7;
        float tauD = g_s[OFF_TAUD];
        float b = 0.f;
        #pragma unroll
        for (int c = 0; c < 3; c++) b += g_s[OFF_S + c * 8 + r] * sx0[n * 3 + c];
        g_s[OFF_CNST + tid] = tauD * b - g_s[OFF_LAM] * g_s[OFF_GAMMA] * tauD * g_s[OFF_SNRM + r];
    }
}

// ---------------------------------------------------------------------------
// k_pass: fused D-update + prox; two phases:
//   phase 1: Dt_new[r] = relu(f[r]*d[r] - tauD*S^T(S(f⊙d)+x) + cnst[r]),
//            accumulate sum(8) + XD(24), write Dt (float2, in place on d_out).
//   phase 2: re-read own just-written chunk (L1/L2-hot), accumulate Gram(36)
//            with packed fma.rn.f32x2.
//   grid(128, 8), 256 threads.
// ---------------------------------------------------------------------------
__global__ void __launch_bounds__(256, 2) k_pass(const float* __restrict__ X,
                                                 float* __restrict__ Dt, int first) {
    const int n = blockIdx.y;
    const int tid = threadIdx.x;

    float Sc[24], fr[8], cn[8];
    #pragma unroll
    for (int i = 0; i < 24; i++) Sc[i] = g_s[OFF_S + i];
    #pragma unroll
    for (int r = 0; r < 8; r++) {
        fr[r] = g_s[OFF_F + n * 8 + r];
        cn[r] = g_s[OFF_CNST + n * 8 + r];
    }
    const float tauD = g_s[OFF_TAUD];

    float a_s[8], a_x[24];
    #pragma unroll
    for (int i = 0; i < 8; i++)  a_s[i] = 0.f;
    #pragma unroll
    for (int i = 0; i < 24; i++) a_x[i] = 0.f;

    const float2* Xp = reinterpret_cast<const float2*>(X + (size_t)n * 3 * P_);
    float2* Dp = reinterpret_cast<float2*>(Dt + (size_t)n * 8 * P_);
    const int base = blockIdx.x * 1024;

    // ---------------- phase 1 ----------------
    #pragma unroll 1
    for (int l = 0; l < 4; l++) {
        int i = base + l * 256 + tid;
        float2 xv0 = Xp[i], xv1 = Xp[i + P2_], xv2 = Xp[i + 2 * P2_];
        float2 dv[8];
        if (!first) {
            #pragma unroll
            for (int r = 0; r < 8; r++) dv[r] = Dp[i + r * P2_];
        }
        #pragma unroll
        for (int j = 0; j < 2; j++) {
            float x0 = j ? xv0.y : xv0.x;
            float x1 = j ? xv1.y : xv1.x;
            float x2 = j ? xv2.y : xv2.x;
            float v[8];
            float t0 = x0, t1 = x1, t2 = x2;
            if (!first) {
                #pragma unroll
                for (int r = 0; r < 8; r++) {
                    float de = fr[r] * (j ? dv[r].y : dv[r].x);
                    v[r] = de;
                    t0 += Sc[r] * de;
                    t1 += Sc[8 + r] * de;
                    t2 += Sc[16 + r] * de;
                }
            } else {
                #pragma unroll
                for (int r = 0; r < 8; r++) v[r] = 0.f;
            }
            #pragma unroll
            for (int r = 0; r < 8; r++) {
                float u = Sc[r] * t0 + Sc[8 + r] * t1 + Sc[16 + r] * t2;
                float val = v[r] + cn[r] - tauD * u;
                val = fmaxf(val, 0.f);
                if (j) dv[r].y = val; else dv[r].x = val;
                a_s[r]      += val;
                a_x[r]      += x0 * val;
                a_x[8 + r]  += x1 * val;
                a_x[16 + r] += x2 * val;
            }
        }
        #pragma unroll
        for (int r = 0; r < 8; r++) Dp[i + r * P2_] = dv[r];
    }

    // reduce sum+XD (32 values): warp shuffle -> smem -> one atomic per value
    __shared__ float sred[8 * 36];
    const int lane = tid & 31, wid = tid >> 5;
    #pragma unroll
    for (int k = 0; k < 8; k++) {
        float vv = a_s[k];
        #pragma unroll
        for (int o = 16; o; o >>= 1) vv += __shfl_xor_sync(0xffffffffu, vv, o);
        if (lane == 0) sred[wid * 32 + k] = vv;
    }
    #pragma unroll
    for (int k = 0; k < 24; k++) {
        float vv = a_x[k];
        #pragma unroll
        for (int o = 16; o; o >>= 1) vv += __shfl_xor_sync(0xffffffffu, vv, o);
        if (lane == 0) sred[wid * 32 + 8 + k] = vv;
    }
    __syncthreads();
    if (tid < 32) {
        float s = 0.f;
        #pragma unroll
        for (int w = 0; w < 8; w++) s += sred[w * 32 + tid];
        int addr = tid < 8 ? OFF_ACCSUM + n * 8 + tid : OFF_XD + n * 24 + (tid - 8);
        atomicAdd(&g_s[addr], s);
    }
    __syncthreads();   // sred reads done before phase-2 reuse

    // ---------------- phase 2: Gram with packed FFMA2 ----------------
    uint64_t a_g[36];
    #pragma unroll
    for (int k = 0; k < 36; k++) a_g[k] = 0ull;
    const uint64_t* Dq = reinterpret_cast<const uint64_t*>(Dp);
    #pragma unroll 1
    for (int l = 0; l < 4; l++) {
        int i = base + l * 256 + tid;
        uint64_t dv[8];
        #pragma unroll
        for (int r = 0; r < 8; r++) dv[r] = Dq[i + r * P2_];
        int gi = 0;
        #pragma unroll
        for (int r = 0; r < 8; r++)
            #pragma unroll
            for (int r2 = r; r2 < 8; r2++) { ffma2(a_g[gi], dv[r], dv[r2]); gi++; }
    }
    #pragma unroll
    for (int k = 0; k < 36; k++) {
        float vv = f2lo(a_g[k]) + f2hi(a_g[k]);
        #pragma unroll
        for (int o = 16; o; o >>= 1) vv += __shfl_xor_sync(0xffffffffu, vv, o);
        if (lane == 0) sred[wid * 36 + k] = vv;
    }
    __syncthreads();
    if (tid < 36) {
        float s = 0.f;
        #pragma unroll
        for (int w = 0; w < 8; w++) s += sred[w * 36 + tid];
        atomicAdd(&g_s[OFF_GRAM + n * 36 + tid], s);
    }
}

// ---------------------------------------------------------------------------
// k_iterBA: B-phase (prox scale scl, x0, tau_S, G, S update + renorm, lazy f),
//           then (if do_a) the next iteration's A-phase prep.
// ---------------------------------------------------------------------------
__global__ void __launch_bounds__(512) k_iterBA(float* __restrict__ out, int last, int do_a) {
    int tid = threadIdx.x;
    __shared__ float s_scl[64], s_sums[64], s_gt[64], s_tr[64];
    __shared__ float s_gram[8][8][8], s_x0[24], s_G[192], s_Sg[24], s_n3[8];
    __shared__ float s_tauS;
    float lam = g_s[OFF_LAM], gam = g_s[OFF_GAMMA], tauD = g_s[OFF_TAUD];

    if (tid < 64) {
        int n = tid >> 3, r = tid & 7;
        float gu = g_s[OFF_GRAM + n * 36 + triIdx(r, r)];
        float L2 = sqrtf(gu);
        float t = L2 - lam * tauD * g_s[OFF_SNRM + r];
        float scl = (t > 0.f ? t : 0.f) / L2 + EPS_;     // faithful to source
        s_scl[tid] = scl;
        float su = scl * g_s[OFF_ACCSUM + tid];
        s_sums[tid] = su;
        s_gt[tid] = gam * su + scl * L2;                 // gamma*sum|Dt| + ||Dt||
        s_tr[tid] = scl * scl * gu;                      // trace contrib
    }
    __syncthreads();
    {
        int n = tid >> 6, r = (tid >> 3) & 7, r2 = tid & 7;
        int lo = min(r, r2), hi = max(r, r2);
        s_gram[n][r][r2] = s_scl[n * 8 + r] * s_scl[n * 8 + r2] *
                           g_s[OFF_GRAM + n * 36 + triIdx(lo, hi)];
    }
    __syncthreads();
    if (tid < 24) {                                      // x0 (S-update, pre-update S)
        int n = tid / 3, c = tid % 3;
        float a = g_s[OFF_MEANX + tid];
        #pragma unroll
        for (int r = 0; r < 8; r++) a += g_s[OFF_S + c * 8 + r] * s_sums[n * 8 + r];
        a *= (1.f / (float)P_);
        s_x0[tid] = a;
        if (last) out[tid] = a;
    }
    if (tid == 64) {
        float s = 0.f;
        for (int k = 0; k < 64; k++) s += s_tr[k];
        s_tauS = 8.f / s;                                // 1/mean_n(trace)
    }
    __syncthreads();
    if (tid < 192) {                                     // G[n,c,r]
        int n = tid / 24, c = (tid / 8) % 3, r = tid & 7;
        float g = s_scl[n * 8 + r] * g_s[OFF_XD + n * 24 + c * 8 + r];
        #pragma unroll
        for (int r2 = 0; r2 < 8; r2++) g += g_s[OFF_S + c * 8 + r2] * s_gram[n][r2][r];
        g -= s_x0[n * 3 + c] * s_sums[n * 8 + r];
        s_G[tid] = g;
    }
    __syncthreads();
    if (tid < 24) {                                      // S_grad[c,r]
        int c = tid / 8, r = tid & 7;
        float mg = 0.f;
        #pragma unroll
        for (int n = 0; n < 8; n++) mg += s_G[n * 24 + c * 8 + r];
        mg *= 0.125f;
        s_Sg[tid] = g_s[OFF_S + c * 8 + r] - s_tauS * mg;
    }
    __syncthreads();
    if (tid < 8) {                                       // S column prox + renorm
        int r = tid;
        float dn = 0.f;
        #pragma unroll
        for (int n = 0; n < 8; n++) dn += s_gt[n * 8 + r];
        dn *= 0.125f;                                    // Dt_nrm[r]
        float n2 = 0.f;
        #pragma unroll
        for (int c = 0; c < 3; c++) n2 += s_Sg[c * 8 + r] * s_Sg[c * 8 + r];
        n2 = sqrtf(n2);
        float t = n2 - lam * s_tauS * dn;
        float sclS = (t > 0.f ? t : 0.f) / (n2 + EPS_);
        float sn[3]; float n3 = 0.f;
        #pragma unroll
        for (int c = 0; c < 3; c++) { sn[c] = s_Sg[c * 8 + r] * sclS; n3 += sn[c] * sn[c]; }
        n3 = sqrtf(n3);
        s_n3[r] = n3;
        float inv = 1.f / (n3 + EPS_);
        #pragma unroll
        for (int c = 0; c < 3; c++) {
            float nv = sn[c] * inv;
            g_s[OFF_S + c * 8 + r] = nv;
            if (last) out[24 + c * 8 + r] = nv;
        }
    }
    __syncthreads();
    if (tid < 64) {                                      // new lazy scale + Dtsum
        int r = tid & 7;
        g_s[OFF_F + tid] = s_scl[tid] * (s_n3[r] + EPS_);
        g_s[OFF_DTSUM + tid] = g_s[OFF_ACCSUM + tid];
    }

    if (!do_a) return;
    __syncthreads();
    // ---------------- A-phase (next iteration prep) ----------------
    for (int i = tid; i < 544; i += blockDim.x) g_s[OFF_ACCSUM + i] = 0.f;
    __shared__ float sStS[64], sx0a[24];
    __syncthreads();
    if (tid < 64) {
        int r = tid >> 3, r2 = tid & 7;
        float a = 0.f;
        #pragma unroll
        for (int c = 0; c < 3; c++) a += g_s[OFF_S + c * 8 + r] * g_s[OFF_S + c * 8 + r2];
        sStS[tid] = a;
    }
    __syncthreads();
    if (tid == 0) {
        float s = 0.f;
        #pragma unroll
        for (int r = 0; r < 8; r++) s += sStS[r * 8 + r];
        g_s[OFF_TAUD] = 1.f / s;
    }
    if (tid >= 32 && tid < 40) {
        int r = tid - 32;
        g_s[OFF_SNRM + r] = sqrtf(sStS[r * 8 + r]);
    }
    if (tid >= 64 && tid < 88) {
        int k = tid - 64, n = k / 3, c = k % 3;
        float acc = g_s[OFF_MEANX + k];
        #pragma unroll
        for (int r = 0; r < 8; r++)
            acc += g_s[OFF_S + c * 8 + r] * g_s[OFF_F + n * 8 + r] * g_s[OFF_DTSUM + n * 8 + r];
        sx0a[k] = acc * (1.f / (float)P_);
    }
    __syncthreads();
    if (tid < 64) {
        int n = tid >> 3, r = tid & 7;
        float tauDn = g_s[OFF_TAUD];
        float b = 0.f;
        #pragma unroll
        for (int c = 0; c < 3; c++) b += g_s[OFF_S + c * 8 + r] * sx0a[n * 3 + c];
        g_s[OFF_CNST + tid] = tauDn * b - g_s[OFF_LAM] * g_s[OFF_GAMMA] * tauDn * g_s[OFF_SNRM + r];
    }
}

// ---------------------------------------------------------------------------
// k_scale: final in-place Dt *= f[n,r]   grid(64, 64), 256 threads
// ---------------------------------------------------------------------------
__global__ void __launch_bounds__(256) k_scale(float* __restrict__ Dt) {
    int y = blockIdx.y;                                  // n*8+r
    float f = g_s[OFF_F + y];
    float4* D = reinterpret_cast<float4*>(Dt + (size_t)y * P_);
    int base = blockIdx.x * 1024;
    #pragma unroll
    for (int l = 0; l < 4; l++) {
        int i = base + l * 256 + threadIdx.x;
        float4 v = D[i];
        v.x *= f; v.y *= f; v.z *= f; v.w *= f;
        D[i] = v;
    }
}

// ---------------------------------------------------------------------------
extern "C" void kernel_launch(void* const* d_in, const int* in_sizes, int n_in,
                              void* d_out, int out_size) {
    const float* X     = (const float*)d_in[0];
    const float* S     = (const float*)d_in[1];
    const float* gamma = (const float*)d_in[2];
    const float* lam   = (const float*)d_in[3];
    float* out = (float*)d_out;
    float* Dt  = out + 48;                               // Dt region of output

    k_init<<<1, 256>>>(S, gamma, lam);
    k_meanx<<<dim3(32, 24), 256>>>(X);
    k_iterA<<<1, 128>>>();
    k_pass<<<dim3(128, 8), 256>>>(X, Dt, 1);
    k_iterBA<<<1, 512>>>(out, 0, 1);
    k_pass<<<dim3(128, 8), 256>>>(X, Dt, 0);
    k_iterBA<<<1, 512>>>(out, 0, 1);
    k_pass<<<dim3(128, 8), 256>>>(X, Dt, 0);
    k_iterBA<<<1, 512>>>(out, 1, 0);
    k_scale<<<dim3(64, 64), 256>>>(Dt);
}

// round 3
// speedup vs baseline: 1.5353x; 1.5353x over previous
#include <cuda_runtime.h>
#include <math.h>

// Problem constants: N=8, C=3, R=8, P=512*512, n_iter=3
#define P_    262144
#define P4_   65536        // float4 count per (n,*) plane
#define EPS_  1e-10f
#define NB    440          // total blocks (8 n-groups x 55)
#define BPN   55           // blocks per n
#define NTHR  128

// ---- device globals (no allocations allowed) ----
__device__ float    g_stats[3 * 544];     // per iter, per n: [0,8) sum, [8,32) XD, [32,68) gram-tri
__device__ float    g_meanx[NB * 3];      // per-block partial sums of X
__device__ unsigned g_count = 0;
__device__ unsigned g_sense = 0;

__device__ __forceinline__ int triIdx(int r, int r2) {   // r <= r2
    return r * 8 - (r * (r - 1)) / 2 + (r2 - r);
}
__device__ __forceinline__ float getc(const float4& v, int j) {
    return j == 0 ? v.x : j == 1 ? v.y : j == 2 ? v.z : v.w;
}
__device__ __forceinline__ void setc(float4& v, int j, float x) {
    if (j == 0) v.x = x; else if (j == 1) v.y = x; else if (j == 2) v.z = x; else v.w = x;
}
__device__ __forceinline__ unsigned ld_acq(unsigned* p) {
    unsigned v;
    asm volatile("ld.acquire.gpu.u32 %0, [%1];" : "=r"(v) : "l"(p) : "memory");
    return v;
}
// grid-wide sense-reversal barrier; all NB blocks guaranteed co-resident
__device__ __forceinline__ void gridsync() {
    __threadfence();
    __syncthreads();
    if (threadIdx.x == 0) {
        unsigned s0 = ld_acq(&g_sense);
        unsigned old = atomicAdd(&g_count, 1u);
        if (old == NB - 1) {
            atomicExch(&g_count, 0u);
            __threadfence();
            atomicAdd(&g_sense, 1u);
        } else {
            while (ld_acq(&g_sense) == s0) __nanosleep(64);
        }
    }
    __syncthreads();
}

// iterA: StS, tauD, x0(own n), cnst(own n). All inputs in shared; redundant per block.
__device__ __forceinline__ void do_iterA(int tid, int n,
        const float* sS, const float* sMX, const float* f_own, const float* acc_own,
        float* cn_own, float* sStS, float* x0c, float* sh_tauD, float lam, float gam) {
    if (tid < 64) {
        int r = tid >> 3, r2 = tid & 7;
        float a = 0.f;
        #pragma unroll
        for (int c = 0; c < 3; c++) a += sS[c * 8 + r] * sS[c * 8 + r2];
        sStS[tid] = a;
    }
    __syncthreads();
    if (tid == 0) {
        float s = 0.f;
        #pragma unroll
        for (int r = 0; r < 8; r++) s += sStS[r * 8 + r];
        *sh_tauD = 1.f / s;
    }
    __syncthreads();
    float tauD = *sh_tauD;
    if (tid < 3) {
        float acc = sMX[n * 3 + tid];
        #pragma unroll
        for (int r = 0; r < 8; r++) acc += sS[tid * 8 + r] * f_own[r] * acc_own[r];
        x0c[tid] = acc * (1.f / (float)P_);
    }
    __syncthreads();
    if (tid < 8) {
        int r = tid;
        float bb = 0.f;
        #pragma unroll
        for (int c = 0; c < 3; c++) bb += sS[c * 8 + r] * x0c[c];
        cn_own[r] = tauD * bb - lam * gam * tauD * sqrtf(sStS[r * 8 + r]);
    }
    __syncthreads();
}

__global__ void __launch_bounds__(NTHR, 3)
k_all(const float* __restrict__ X, const float* __restrict__ Sin,
      const float* __restrict__ gamma_, const float* __restrict__ lam_,
      float* __restrict__ out) {
    const int tid   = threadIdx.x;
    const int b     = blockIdx.x;
    const int n     = b / BPN;
    const int local = b % BPN;
    const int s4    = (P4_ * local) / BPN;
    const int e4    = (P4_ * (local + 1)) / BPN;
    const int lane  = tid & 31, wid = tid >> 5;

    __shared__ float sS[24], sMX[24], f_own[8], cn_own[8], acc_own[8], x0c[3];
    __shared__ float sh_tauD, sh_lam, sh_gam;
    __shared__ float s_scl[64], s_sums[64], s_gt[64], s_tr[64];
    __shared__ float s_gram[8][8][8], s_x0[24], s_G[192], s_Sg[24], s_n3[8], s_tauS;
    __shared__ float sStS[64];
    __shared__ float sred[4 * 68];

    if (tid < 24) sS[tid] = Sin[tid];
    if (tid == 24) sh_gam = fabsf(gamma_[0]);
    if (tid == 25) sh_lam = fabsf(lam_[0]);
    if (tid < 8) { f_own[tid] = 0.f; acc_own[tid] = 0.f; }
    { int idx = b * NTHR + tid; if (idx < 3 * 544) g_stats[idx] = 0.f; }

    const float4* Xp = reinterpret_cast<const float4*>(X) + (size_t)n * 3 * P4_;
    float4* Dp = reinterpret_cast<float4*>(out + 48) + (size_t)n * 8 * P4_;

    // ---- meanX partials over own range ----
    {
        float m0 = 0.f, m1 = 0.f, m2 = 0.f;
        for (int i = s4 + tid; i < e4; i += NTHR) {
            float4 a = Xp[i], bb = Xp[i + P4_], c = Xp[i + 2 * P4_];
            m0 += a.x + a.y + a.z + a.w;
            m1 += bb.x + bb.y + bb.z + bb.w;
            m2 += c.x + c.y + c.z + c.w;
        }
        #pragma unroll
        for (int o = 16; o; o >>= 1) {
            m0 += __shfl_xor_sync(~0u, m0, o);
            m1 += __shfl_xor_sync(~0u, m1, o);
            m2 += __shfl_xor_sync(~0u, m2, o);
        }
        if (lane == 0) { sred[wid * 3 + 0] = m0; sred[wid * 3 + 1] = m1; sred[wid * 3 + 2] = m2; }
        __syncthreads();
        if (tid < 3) {
            float s = 0.f;
            #pragma unroll
            for (int w = 0; w < 4; w++) s += sred[w * 3 + tid];
            g_meanx[b * 3 + tid] = s;
        }
    }

    gridsync();   // sync 1: zeroed stats + meanx partials visible

    // reduce meanx partials redundantly
    if (tid < 24) {
        int nn = tid / 3, cc = tid % 3;
        float s = 0.f;
        for (int j = 0; j < BPN; j++) s += g_meanx[(nn * BPN + j) * 3 + cc];
        sMX[tid] = s;
    }
    __syncthreads();
    const float lam = sh_lam, gam = sh_gam;

    do_iterA(tid, n, sS, sMX, f_own, acc_own, cn_own, sStS, x0c, &sh_tauD, lam, gam);

    for (int it = 0; it < 3; it++) {
        // ================= fused pass =================
        {
            float Sc[24], fr[8], cn[8];
            #pragma unroll
            for (int i = 0; i < 24; i++) Sc[i] = sS[i];
            #pragma unroll
            for (int r = 0; r < 8; r++) { fr[r] = f_own[r]; cn[r] = cn_own[r]; }
            const float tauD = sh_tauD;
            float a_s[8], a_x[24], a_g[36];
            #pragma unroll
            for (int i = 0; i < 8; i++)  a_s[i] = 0.f;
            #pragma unroll
            for (int i = 0; i < 24; i++) a_x[i] = 0.f;
            #pragma unroll
            for (int i = 0; i < 36; i++) a_g[i] = 0.f;

            if (it == 0) {
                for (int i = s4 + tid; i < e4; i += NTHR) {
                    float4 xv0 = Xp[i], xv1 = Xp[i + P4_], xv2 = Xp[i + 2 * P4_];
                    float4 dv[8];
                    #pragma unroll
                    for (int j = 0; j < 4; j++) {
                        float x0 = getc(xv0, j), x1 = getc(xv1, j), x2 = getc(xv2, j);
                        float v[8];
                        #pragma unroll
                        for (int r = 0; r < 8; r++) {
                            float u = Sc[r] * x0 + Sc[8 + r] * x1 + Sc[16 + r] * x2;
                            float val = fmaxf(cn[r] - tauD * u, 0.f);
                            v[r] = val;
                            setc(dv[r], j, val);
                            a_s[r]      += val;
                            a_x[r]      += x0 * val;
                            a_x[8 + r]  += x1 * val;
                            a_x[16 + r] += x2 * val;
                        }
                        int gi = 0;
                        #pragma unroll
                        for (int r = 0; r < 8; r++)
                            #pragma unroll
                            for (int r2 = r; r2 < 8; r2++) { a_g[gi] += v[r] * v[r2]; gi++; }
                    }
                    #pragma unroll
                    for (int r = 0; r < 8; r++) Dp[i + r * P4_] = dv[r];
                }
            } else {
                for (int i = s4 + tid; i < e4; i += NTHR) {
                    float4 xv0 = Xp[i], xv1 = Xp[i + P4_], xv2 = Xp[i + 2 * P4_];
                    float4 dv[8];
                    #pragma unroll
                    for (int r = 0; r < 8; r++) dv[r] = Dp[i + r * P4_];
                    #pragma unroll
                    for (int j = 0; j < 4; j++) {
                        float x0 = getc(xv0, j), x1 = getc(xv1, j), x2 = getc(xv2, j);
                        float de[8], v[8];
                        float t0 = x0, t1 = x1, t2 = x2;
                        #pragma unroll
                        for (int r = 0; r < 8; r++) {
                            float d = fr[r] * getc(dv[r], j);
                            de[r] = d;
                            t0 += Sc[r] * d;
                            t1 += Sc[8 + r] * d;
                            t2 += Sc[16 + r] * d;
                        }
                        #pragma unroll
                        for (int r = 0; r < 8; r++) {
                            float u = Sc[r] * t0 + Sc[8 + r] * t1 + Sc[16 + r] * t2;
                            float val = fmaxf(de[r] + cn[r] - tauD * u, 0.f);
                            v[r] = val;
                            setc(dv[r], j, val);
                            a_s[r]      += val;
                            a_x[r]      += x0 * val;
                            a_x[8 + r]  += x1 * val;
                            a_x[16 + r] += x2 * val;
                        }
                        int gi = 0;
                        #pragma unroll
                        for (int r = 0; r < 8; r++)
                            #pragma unroll
                            for (int r2 = r; r2 < 8; r2++) { a_g[gi] += v[r] * v[r2]; gi++; }
                    }
                    #pragma unroll
                    for (int r = 0; r < 8; r++) Dp[i + r * P4_] = dv[r];
                }
            }

            // flush 68 accumulators: warp shuffle -> smem -> one atomic each
            __syncthreads();   // sred reuse safety
            #pragma unroll
            for (int k = 0; k < 8; k++) {
                float vv = a_s[k];
                #pragma unroll
                for (int o = 16; o; o >>= 1) vv += __shfl_xor_sync(~0u, vv, o);
                if (lane == 0) sred[wid * 68 + k] = vv;
            }
            #pragma unroll
            for (int k = 0; k < 24; k++) {
                float vv = a_x[k];
                #pragma unroll
                for (int o = 16; o; o >>= 1) vv += __shfl_xor_sync(~0u, vv, o);
                if (lane == 0) sred[wid * 68 + 8 + k] = vv;
            }
            #pragma unroll
            for (int k = 0; k < 36; k++) {
                float vv = a_g[k];
                #pragma unroll
                for (int o = 16; o; o >>= 1) vv += __shfl_xor_sync(~0u, vv, o);
                if (lane == 0) sred[wid * 68 + 32 + k] = vv;
            }
            __syncthreads();
            if (tid < 68) {
                float s = sred[tid] + sred[68 + tid] + sred[136 + tid] + sred[204 + tid];
                atomicAdd(&g_stats[it * 544 + n * 68 + tid], s);
            }
        }

        gridsync();   // stats of this iteration complete

        // ================= iterB (redundant per block) =================
        {
            const int last = (it == 2);
            const float* st = &g_stats[it * 544];
            const float tauD = sh_tauD;
            if (tid < 64) {
                int nn = tid >> 3, r = tid & 7;
                float gu = st[nn * 68 + 32 + triIdx(r, r)];
                float L2 = sqrtf(gu);
                float t = L2 - lam * tauD * sqrtf(sStS[r * 8 + r]);
                float scl = fmaxf(t, 0.f) / L2 + EPS_;        // faithful to source
                s_scl[tid] = scl;
                float su = scl * st[nn * 68 + r];
                s_sums[tid] = su;
                s_gt[tid] = gam * su + scl * L2;
                s_tr[tid] = scl * scl * gu;
            }
            __syncthreads();
            for (int idx = tid; idx < 512; idx += NTHR) {
                int nn = idx >> 6, r = (idx >> 3) & 7, r2 = idx & 7;
                int lo = min(r, r2), hi = max(r, r2);
                s_gram[nn][r][r2] = s_scl[nn * 8 + r] * s_scl[nn * 8 + r2] *
                                    st[nn * 68 + 32 + triIdx(lo, hi)];
            }
            __syncthreads();
            if (tid < 24) {
                int nn = tid / 3, c = tid % 3;
                float a = sMX[tid];
                #pragma unroll
                for (int r = 0; r < 8; r++) a += sS[c * 8 + r] * s_sums[nn * 8 + r];
                a *= (1.f / (float)P_);
                s_x0[tid] = a;
                if (last && b == 0) out[tid] = a;
            }
            if (tid == 64) {
                float s = 0.f;
                for (int k = 0; k < 64; k++) s += s_tr[k];
                s_tauS = 8.f / s;
            }
            __syncthreads();
            for (int idx = tid; idx < 192; idx += NTHR) {
                int nn = idx / 24, c = (idx / 8) % 3, r = idx & 7;
                float g = s_scl[nn * 8 + r] * st[nn * 68 + 8 + c * 8 + r];
                #pragma unroll
                for (int r2 = 0; r2 < 8; r2++) g += sS[c * 8 + r2] * s_gram[nn][r2][r];
                g -= s_x0[nn * 3 + c] * s_sums[nn * 8 + r];
                s_G[idx] = g;
            }
            __syncthreads();
            if (tid < 24) {
                int c = tid / 8, r = tid & 7;
                float mg = 0.f;
                #pragma unroll
                for (int nn = 0; nn < 8; nn++) mg += s_G[nn * 24 + c * 8 + r];
                mg *= 0.125f;
                s_Sg[tid] = sS[c * 8 + r] - s_tauS * mg;
            }
            __syncthreads();
            if (tid < 8) {
                int r = tid;
                float dn = 0.f;
                #pragma unroll
                for (int nn = 0; nn < 8; nn++) dn += s_gt[nn * 8 + r];
                dn *= 0.125f;
                float n2 = 0.f;
                #pragma unroll
                for (int c = 0; c < 3; c++) n2 += s_Sg[c * 8 + r] * s_Sg[c * 8 + r];
                n2 = sqrtf(n2);
                float t = n2 - lam * s_tauS * dn;
                float sclS = fmaxf(t, 0.f) / (n2 + EPS_);
                float sn[3]; float n3 = 0.f;
                #pragma unroll
                for (int c = 0; c < 3; c++) { sn[c] = s_Sg[c * 8 + r] * sclS; n3 += sn[c] * sn[c]; }
                n3 = sqrtf(n3);
                s_n3[r] = n3;
                float inv = 1.f / (n3 + EPS_);
                #pragma unroll
                for (int c = 0; c < 3; c++) {
                    float nv = sn[c] * inv;
                    sS[c * 8 + r] = nv;
                    if (last && b == 0) out[24 + c * 8 + r] = nv;
                }
            }
            __syncthreads();
            if (tid < 8) {
                f_own[tid]  = s_scl[n * 8 + tid] * (s_n3[tid] + EPS_);
                acc_own[tid] = st[n * 68 + tid];
            }
            __syncthreads();
            if (!last)
                do_iterA(tid, n, sS, sMX, f_own, acc_own, cn_own, sStS, x0c, &sh_tauD, lam, gam);
        }
    }

    // ================= final scale (L2-hot, own range) =================
    {
        float f[8];
        #pragma unroll
        for (int r = 0; r < 8; r++) f[r] = f_own[r];
        for (int i = s4 + tid; i < e4; i += NTHR) {
            #pragma unroll
            for (int r = 0; r < 8; r++) {
                float4 v = Dp[i + r * P4_];
                v.x *= f[r]; v.y *= f[r]; v.z *= f[r]; v.w *= f[r];
                Dp[i + r * P4_] = v;
            }
        }
    }
}

// ---------------------------------------------------------------------------
extern "C" void kernel_launch(void* const* d_in, const int* in_sizes, int n_in,
                              void* d_out, int out_size) {
    const float* X     = (const float*)d_in[0];
    const float* S     = (const float*)d_in[1];
    const float* gamma = (const float*)d_in[2];
    const float* lam   = (const float*)d_in[3];
    float* out = (float*)d_out;
    k_all<<<NB, NTHR>>>(X, S, gamma, lam, out);
}

// round 4
// speedup vs baseline: 1.8405x; 1.1988x over previous
#include <cuda_runtime.h>
#include <cuda_fp16.h>
#include <math.h>

// Problem constants: N=8, C=3, R=8, P=512*512, n_iter=3
#define P_    262144
#define P4_   65536        // float4 count per (n,*) plane
#define PH2_  131072       // half2 count per (n,r) plane
#define EPS_  1e-10f
#define NB    440          // total blocks (8 n-groups x 55)
#define BPN   55           // blocks per n
#define NTHR  128

// ---- device globals (no allocations allowed) ----
__device__ float    g_stats[3 * 544];     // per iter, per n: [0,8) sum, [8,32) XD, [32,68) gram-tri
__device__ float    g_meanx[NB * 3];      // per-block partial sums of X
__device__ unsigned g_count = 0;
__device__ unsigned g_sense = 0;
__device__ __half2  g_dt[(size_t)64 * PH2_];   // fp16 intermediate Dt, 8n x 8r planes

__device__ __forceinline__ int triIdx(int r, int r2) {   // r <= r2
    return r * 8 - (r * (r - 1)) / 2 + (r2 - r);
}
__device__ __forceinline__ float getc(const float4& v, int j) {
    return j == 0 ? v.x : j == 1 ? v.y : j == 2 ? v.z : v.w;
}
__device__ __forceinline__ void setc(float4& v, int j, float x) {
    if (j == 0) v.x = x; else if (j == 1) v.y = x; else if (j == 2) v.z = x; else v.w = x;
}
__device__ __forceinline__ float4 h4tof4(uint2 u) {
    __half2 a = *reinterpret_cast<__half2*>(&u.x);
    __half2 b = *reinterpret_cast<__half2*>(&u.y);
    float2 fa = __half22float2(a), fb = __half22float2(b);
    return make_float4(fa.x, fa.y, fb.x, fb.y);
}
__device__ __forceinline__ uint2 f4toh4(float4 v) {
    __half2 a = __floats2half2_rn(v.x, v.y);
    __half2 b = __floats2half2_rn(v.z, v.w);
    uint2 u;
    u.x = *reinterpret_cast<unsigned*>(&a);
    u.y = *reinterpret_cast<unsigned*>(&b);
    return u;
}
__device__ __forceinline__ unsigned ld_acq(unsigned* p) {
    unsigned v;
    asm volatile("ld.acquire.gpu.u32 %0, [%1];" : "=r"(v) : "l"(p) : "memory");
    return v;
}
// grid-wide sense-reversal barrier; all NB blocks co-resident by construction
__device__ __forceinline__ void gridsync() {
    __threadfence();
    __syncthreads();
    if (threadIdx.x == 0) {
        unsigned s0 = ld_acq(&g_sense);
        unsigned old = atomicAdd(&g_count, 1u);
        if (old == NB - 1) {
            atomicExch(&g_count, 0u);
            __threadfence();
            atomicAdd(&g_sense, 1u);
        } else {
            while (ld_acq(&g_sense) == s0) __nanosleep(64);
        }
    }
    __syncthreads();
}

// iterA: StS, tauD, x0(own n), cnst(own n). Redundant per block.
__device__ __forceinline__ void do_iterA(int tid, int n,
        const float* sS, const float* sMX, const float* f_own, const float* acc_own,
        float* cn_own, float* sStS, float* x0c, float* sh_tauD, float lam, float gam) {
    if (tid < 64) {
        int r = tid >> 3, r2 = tid & 7;
        float a = 0.f;
        #pragma unroll
        for (int c = 0; c < 3; c++) a += sS[c * 8 + r] * sS[c * 8 + r2];
        sStS[tid] = a;
    }
    __syncthreads();
    if (tid == 0) {
        float s = 0.f;
        #pragma unroll
        for (int r = 0; r < 8; r++) s += sStS[r * 8 + r];
        *sh_tauD = 1.f / s;
    }
    __syncthreads();
    float tauD = *sh_tauD;
    if (tid < 3) {
        float acc = sMX[n * 3 + tid];
        #pragma unroll
        for (int r = 0; r < 8; r++) acc += sS[tid * 8 + r] * f_own[r] * acc_own[r];
        x0c[tid] = acc * (1.f / (float)P_);
    }
    __syncthreads();
    if (tid < 8) {
        int r = tid;
        float bb = 0.f;
        #pragma unroll
        for (int c = 0; c < 3; c++) bb += sS[c * 8 + r] * x0c[c];
        cn_own[r] = tauD * bb - lam * gam * tauD * sqrtf(sStS[r * 8 + r]);
    }
    __syncthreads();
}

__global__ void __launch_bounds__(NTHR, 3)
k_all(const float* __restrict__ X, const float* __restrict__ Sin,
      const float* __restrict__ gamma_, const float* __restrict__ lam_,
      float* __restrict__ out) {
    const int tid   = threadIdx.x;
    const int b     = blockIdx.x;
    const int n     = b / BPN;
    const int local = b % BPN;
    const int s4    = (P4_ * local) / BPN;
    const int e4    = (P4_ * (local + 1)) / BPN;
    const int lane  = tid & 31, wid = tid >> 5;

    __shared__ float sS[24], sMX[24], f_own[8], cn_own[8], acc_own[8], x0c[3];
    __shared__ float f_sav[8], s_Sold[24];
    __shared__ float sh_tauD, sh_lam, sh_gam;
    __shared__ float s_scl[64], s_sums[64], s_gt[64], s_tr[64];
    __shared__ float s_gram[8][8][8], s_x0[24], s_G[192], s_Sg[24], s_n3[8], s_tauS;
    __shared__ float sStS[64];
    __shared__ float sred[4 * 68];

    if (tid < 24) sS[tid] = Sin[tid];
    if (tid == 24) sh_gam = fabsf(gamma_[0]);
    if (tid == 25) sh_lam = fabsf(lam_[0]);
    if (tid < 8) { f_own[tid] = 0.f; acc_own[tid] = 0.f; }
    { int idx = b * NTHR + tid; if (idx < 3 * 544) g_stats[idx] = 0.f; }

    const float4* Xp = reinterpret_cast<const float4*>(X) + (size_t)n * 3 * P4_;
    uint2* Dq = reinterpret_cast<uint2*>(g_dt) + (size_t)n * 8 * P4_;   // fp16 planes
    float4* Dpout = reinterpret_cast<float4*>(out + 48) + (size_t)n * 8 * P4_;

    // ---- meanX partials over own range ----
    {
        float m0 = 0.f, m1 = 0.f, m2 = 0.f;
        for (int i = s4 + tid; i < e4; i += NTHR) {
            float4 a = Xp[i], bb = Xp[i + P4_], c = Xp[i + 2 * P4_];
            m0 += a.x + a.y + a.z + a.w;
            m1 += bb.x + bb.y + bb.z + bb.w;
            m2 += c.x + c.y + c.z + c.w;
        }
        #pragma unroll
        for (int o = 16; o; o >>= 1) {
            m0 += __shfl_xor_sync(~0u, m0, o);
            m1 += __shfl_xor_sync(~0u, m1, o);
            m2 += __shfl_xor_sync(~0u, m2, o);
        }
        if (lane == 0) { sred[wid * 3 + 0] = m0; sred[wid * 3 + 1] = m1; sred[wid * 3 + 2] = m2; }
        __syncthreads();
        if (tid < 3) {
            float s = 0.f;
            #pragma unroll
            for (int w = 0; w < 4; w++) s += sred[w * 3 + tid];
            g_meanx[b * 3 + tid] = s;
        }
    }

    gridsync();   // sync 1: zeroed stats + meanx partials visible

    if (tid < 24) {
        int nn = tid / 3, cc = tid % 3;
        float s = 0.f;
        for (int j = 0; j < BPN; j++) s += g_meanx[(nn * BPN + j) * 3 + cc];
        sMX[tid] = s;
    }
    __syncthreads();
    const float lam = sh_lam, gam = sh_gam;

    do_iterA(tid, n, sS, sMX, f_own, acc_own, cn_own, sStS, x0c, &sh_tauD, lam, gam);

    for (int it = 0; it < 3; it++) {
        // ================= fused pass =================
        {
            float Sc[24], fr[8], cn[8];
            #pragma unroll
            for (int i = 0; i < 24; i++) Sc[i] = sS[i];
            #pragma unroll
            for (int r = 0; r < 8; r++) { fr[r] = f_own[r]; cn[r] = cn_own[r]; }
            const float tauD = sh_tauD;
            float a_s[8], a_x[24], a_g[36];
            #pragma unroll
            for (int i = 0; i < 8; i++)  a_s[i] = 0.f;
            #pragma unroll
            for (int i = 0; i < 24; i++) a_x[i] = 0.f;
            #pragma unroll
            for (int i = 0; i < 36; i++) a_g[i] = 0.f;

            if (it == 0) {
                for (int i = s4 + tid; i < e4; i += NTHR) {
                    float4 xv0 = Xp[i], xv1 = Xp[i + P4_], xv2 = Xp[i + 2 * P4_];
                    float4 dv[8];
                    #pragma unroll
                    for (int j = 0; j < 4; j++) {
                        float x0 = getc(xv0, j), x1 = getc(xv1, j), x2 = getc(xv2, j);
                        float v[8];
                        #pragma unroll
                        for (int r = 0; r < 8; r++) {
                            float u = Sc[r] * x0 + Sc[8 + r] * x1 + Sc[16 + r] * x2;
                            float val = fmaxf(cn[r] - tauD * u, 0.f);
                            v[r] = val;
                            setc(dv[r], j, val);
                            a_s[r]      += val;
                            a_x[r]      += x0 * val;
                            a_x[8 + r]  += x1 * val;
                            a_x[16 + r] += x2 * val;
                        }
                        int gi = 0;
                        #pragma unroll
                        for (int r = 0; r < 8; r++)
                            #pragma unroll
                            for (int r2 = r; r2 < 8; r2++) { a_g[gi] += v[r] * v[r2]; gi++; }
                    }
                    #pragma unroll
                    for (int r = 0; r < 8; r++) Dq[i + r * P4_] = f4toh4(dv[r]);
                }
            } else {
                const int do_store = (it == 1);
                for (int i = s4 + tid; i < e4; i += NTHR) {
                    float4 xv0 = Xp[i], xv1 = Xp[i + P4_], xv2 = Xp[i + 2 * P4_];
                    float4 dv[8];
                    #pragma unroll
                    for (int r = 0; r < 8; r++) dv[r] = h4tof4(Dq[i + r * P4_]);
                    #pragma unroll
                    for (int j = 0; j < 4; j++) {
                        float x0 = getc(xv0, j), x1 = getc(xv1, j), x2 = getc(xv2, j);
                        float de[8], v[8];
                        float t0 = x0, t1 = x1, t2 = x2;
                        #pragma unroll
                        for (int r = 0; r < 8; r++) {
                            float d = fr[r] * getc(dv[r], j);
                            de[r] = d;
                            t0 += Sc[r] * d;
                            t1 += Sc[8 + r] * d;
                            t2 += Sc[16 + r] * d;
                        }
                        #pragma unroll
                        for (int r = 0; r < 8; r++) {
                            float u = Sc[r] * t0 + Sc[8 + r] * t1 + Sc[16 + r] * t2;
                            float val = fmaxf(de[r] + cn[r] - tauD * u, 0.f);
                            v[r] = val;
                            setc(dv[r], j, val);
                            a_s[r]      += val;
                            a_x[r]      += x0 * val;
                            a_x[8 + r]  += x1 * val;
                            a_x[16 + r] += x2 * val;
                        }
                        int gi = 0;
                        #pragma unroll
                        for (int r = 0; r < 8; r++)
                            #pragma unroll
                            for (int r2 = r; r2 < 8; r2++) { a_g[gi] += v[r] * v[r2]; gi++; }
                    }
                    if (do_store) {
                        #pragma unroll
                        for (int r = 0; r < 8; r++) Dq[i + r * P4_] = f4toh4(dv[r]);
                    }
                }
            }

            // flush 68 accumulators: warp shuffle -> smem -> one atomic each
            __syncthreads();
            #pragma unroll
            for (int k = 0; k < 8; k++) {
                float vv = a_s[k];
                #pragma unroll
                for (int o = 16; o; o >>= 1) vv += __shfl_xor_sync(~0u, vv, o);
                if (lane == 0) sred[wid * 68 + k] = vv;
            }
            #pragma unroll
            for (int k = 0; k < 24; k++) {
                float vv = a_x[k];
                #pragma unroll
                for (int o = 16; o; o >>= 1) vv += __shfl_xor_sync(~0u, vv, o);
                if (lane == 0) sred[wid * 68 + 8 + k] = vv;
            }
            #pragma unroll
            for (int k = 0; k < 36; k++) {
                float vv = a_g[k];
                #pragma unroll
                for (int o = 16; o; o >>= 1) vv += __shfl_xor_sync(~0u, vv, o);
                if (lane == 0) sred[wid * 68 + 32 + k] = vv;
            }
            __syncthreads();
            if (tid < 68) {
                float s = sred[tid] + sred[68 + tid] + sred[136 + tid] + sred[204 + tid];
                atomicAdd(&g_stats[it * 544 + n * 68 + tid], s);
            }
        }

        gridsync();   // stats of this iteration complete

        // ================= iterB (redundant per block) =================
        {
            const int last = (it == 2);
            const float* st = &g_stats[it * 544];
            const float tauD = sh_tauD;
            if (last) {
                if (tid < 8)  f_sav[tid]  = f_own[tid];   // fr for final recompute
                if (tid < 24) s_Sold[tid] = sS[tid];      // pre-update S for final recompute
            }
            if (tid < 64) {
                int nn = tid >> 3, r = tid & 7;
                float gu = st[nn * 68 + 32 + triIdx(r, r)];
                float L2 = sqrtf(gu);
                float t = L2 - lam * tauD * sqrtf(sStS[r * 8 + r]);
                float scl = fmaxf(t, 0.f) / L2 + EPS_;        // faithful to source
                s_scl[tid] = scl;
                float su = scl * st[nn * 68 + r];
                s_sums[tid] = su;
                s_gt[tid] = gam * su + scl * L2;
                s_tr[tid] = scl * scl * gu;
            }
            __syncthreads();
            for (int idx = tid; idx < 512; idx += NTHR) {
                int nn = idx >> 6, r = (idx >> 3) & 7, r2 = idx & 7;
                int lo = min(r, r2), hi = max(r, r2);
                s_gram[nn][r][r2] = s_scl[nn * 8 + r] * s_scl[nn * 8 + r2] *
                                    st[nn * 68 + 32 + triIdx(lo, hi)];
            }
            __syncthreads();
            if (tid < 24) {
                int nn = tid / 3, c = tid % 3;
                float a = sMX[tid];
                #pragma unroll
                for (int r = 0; r < 8; r++) a += sS[c * 8 + r] * s_sums[nn * 8 + r];
                a *= (1.f / (float)P_);
                s_x0[tid] = a;
                if (last && b == 0) out[tid] = a;
            }
            if (tid == 64) {
                float s = 0.f;
                for (int k = 0; k < 64; k++) s += s_tr[k];
                s_tauS = 8.f / s;
            }
            __syncthreads();
            for (int idx = tid; idx < 192; idx += NTHR) {
                int nn = idx / 24, c = (idx / 8) % 3, r = idx & 7;
                float g = s_scl[nn * 8 + r] * st[nn * 68 + 8 + c * 8 + r];
                #pragma unroll
                for (int r2 = 0; r2 < 8; r2++) g += sS[c * 8 + r2] * s_gram[nn][r2][r];
                g -= s_x0[nn * 3 + c] * s_sums[nn * 8 + r];
                s_G[idx] = g;
            }
            __syncthreads();
            if (tid < 24) {
                int c = tid / 8, r = tid & 7;
                float mg = 0.f;
                #pragma unroll
                for (int nn = 0; nn < 8; nn++) mg += s_G[nn * 24 + c * 8 + r];
                mg *= 0.125f;
                s_Sg[tid] = sS[c * 8 + r] - s_tauS * mg;
            }
            __syncthreads();
            if (tid < 8) {
                int r = tid;
                float dn = 0.f;
                #pragma unroll
                for (int nn = 0; nn < 8; nn++) dn += s_gt[nn * 8 + r];
                dn *= 0.125f;
                float n2 = 0.f;
                #pragma unroll
                for (int c = 0; c < 3; c++) n2 += s_Sg[c * 8 + r] * s_Sg[c * 8 + r];
                n2 = sqrtf(n2);
                float t = n2 - lam * s_tauS * dn;
                float sclS = fmaxf(t, 0.f) / (n2 + EPS_);
                float sn[3]; float n3 = 0.f;
                #pragma unroll
                for (int c = 0; c < 3; c++) { sn[c] = s_Sg[c * 8 + r] * sclS; n3 += sn[c] * sn[c]; }
                n3 = sqrtf(n3);
                s_n3[r] = n3;
                float inv = 1.f / (n3 + EPS_);
                #pragma unroll
                for (int c = 0; c < 3; c++) {
                    float nv = sn[c] * inv;
                    sS[c * 8 + r] = nv;
                    if (last && b == 0) out[24 + c * 8 + r] = nv;
                }
            }
            __syncthreads();
            if (tid < 8) {
                f_own[tid]  = s_scl[n * 8 + tid] * (s_n3[tid] + EPS_);
                acc_own[tid] = st[n * 68 + tid];
            }
            __syncthreads();
            if (!last)
                do_iterA(tid, n, sS, sMX, f_own, acc_own, cn_own, sStS, x0c, &sh_tauD, lam, gam);
        }
    }

    // ====== final pass: recompute it=2 values (identical math, pre-update S,
    //        saved fr/cn) and write f32 output scaled by final lazy factor. ======
    {
        float Sc[24], fr[8], cn[8], fs[8];
        #pragma unroll
        for (int i = 0; i < 24; i++) Sc[i] = s_Sold[i];
        #pragma unroll
        for (int r = 0; r < 8; r++) {
            fr[r] = f_sav[r];
            cn[r] = cn_own[r];
            fs[r] = f_own[r];
        }
        const float tauD = sh_tauD;
        for (int i = s4 + tid; i < e4; i += NTHR) {
            float4 xv0 = Xp[i], xv1 = Xp[i + P4_], xv2 = Xp[i + 2 * P4_];
            float4 dv[8];
            #pragma unroll
            for (int r = 0; r < 8; r++) dv[r] = h4tof4(Dq[i + r * P4_]);
            #pragma unroll
            for (int j = 0; j < 4; j++) {
                float x0 = getc(xv0, j), x1 = getc(xv1, j), x2 = getc(xv2, j);
                float de[8];
                float t0 = x0, t1 = x1, t2 = x2;
                #pragma unroll
                for (int r = 0; r < 8; r++) {
                    float d = fr[r] * getc(dv[r], j);
                    de[r] = d;
                    t0 += Sc[r] * d;
                    t1 += Sc[8 + r] * d;
                    t2 += Sc[16 + r] * d;
                }
                #pragma unroll
                for (int r = 0; r < 8; r++) {
                    float u = Sc[r] * t0 + Sc[8 + r] * t1 + Sc[16 + r] * t2;
                    float val = fmaxf(de[r] + cn[r] - tauD * u, 0.f);
                    setc(dv[r], j, val * fs[r]);
                }
            }
            #pragma unroll
            for (int r = 0; r < 8; r++) __stcs(&Dpout[i + r * P4_], dv[r]);
        }
    }
}

extern "C" void kernel_launch(void* const* d_in, const int* in_sizes, int n_in,
                              void* d_out, int out_size) {
    const float* X     = (const float*)d_in[0];
    const float* S     = (const float*)d_in[1];
    const float* gamma = (const float*)d_in[2];
    const float* lam   = (const float*)d_in[3];
    float* out = (float*)d_out;
    k_all<<<NB, NTHR>>>(X, S, gamma, lam, out);
}